// round 17
// baseline (speedup 1.0000x reference)
#include <cuda_runtime.h>

// out[n,i] = sum_{m<K} W[i, m*D+i] * h_r[n, m*D+i] + b[i]
// N=8192, D=1024, K=8. 256MB read + 32MB write.
// SINGLE-KERNEL design: column-sliced CTAs gather their own weights.
//   - 608 CTAs (4/SM); slice s = bid%4 owns columns [256s, 256s+256).
//   - Each CTA gathers only K*256 = 2048 diagonal weights (64KB sectors,
//     ~1us overlappable prologue) instead of all 8192 -> no 2nd kernel,
//     no PDL, no inter-kernel gap (was 0.1-4.2us of replay jitter).
//   - 4 row-subgroups x 64 threads: 4 rows/iteration, 1KB contiguous
//     reads per m-chunk, MLP=8 __ldcs, write-back stores (proven body).

constexpr int D = 1024;
constexpr int K = 8;
constexpr int KD = K * D;                     // 8192
constexpr int THREADS = 256;
constexpr int NSLICE = 4;
constexpr int SLICE_COLS = D / NSLICE;        // 256 columns per slice
constexpr int SLICE_F4 = SLICE_COLS / 4;      // 64 float4 per slice
constexpr int CTAS_PER_SM = 4;
constexpr int NUM_SMS = 152;                  // GB300
constexpr int GRID = CTAS_PER_SM * NUM_SMS;   // 608
constexpr int CTAS_PER_SLICE = GRID / NSLICE; // 152
constexpr int ROW_GROUPS = 4;                 // 64 threads each
constexpr int ROW_STRIDE = CTAS_PER_SLICE * ROW_GROUPS;  // 608 rows/iter

__global__ __launch_bounds__(THREADS, CTAS_PER_SM)
void imputation_kernel(const float* __restrict__ h_r,
                       const float* __restrict__ W,
                       const float* __restrict__ b,
                       float* __restrict__ out,
                       int n_rows) {
    __shared__ float wd[K][SLICE_COLS];   // 8 KB: this slice's diagonal

    const int t = threadIdx.x;
    const int s = blockIdx.x & (NSLICE - 1);       // column slice 0..3
    const int cta_s = blockIdx.x >> 2;             // 0..151 within slice
    const int tg = t >> 6;                         // row subgroup 0..3
    const int tl = t & 63;                         // lane within subgroup

    // ---- Prologue: gather this slice's 2048 diagonal weights ----
    // Thread t owns column i = s*256 + t; loads all K=8 m-values for it
    // (8 independent scattered loads, MLP=8; 64KB of sectors per CTA,
    // L2-hit after the first CTAs touch the 256KB unique set).
    {
        const int i = s * SLICE_COLS + t;          // global column
        const size_t base = (size_t)i * KD + i;    // W[i, i]
        #pragma unroll
        for (int m = 0; m < K; m++) {
            wd[m][t] = __ldg(&W[base + (size_t)m * D]);
        }
    }
    // Bias for this thread's 4 columns (same for all row subgroups).
    const float4 breg =
        reinterpret_cast<const float4*>(b)[s * SLICE_F4 + tl];

    const float4* __restrict__ h4 = reinterpret_cast<const float4*>(h_r);
    float4* __restrict__ o4 = reinterpret_cast<float4*>(out);

    __syncthreads();

    // ---- Streaming loop: subgroup tg handles row n, 4 rows per CTA/iter ----
    for (int n = cta_s * ROW_GROUPS + tg; n < n_rows; n += ROW_STRIDE) {
        const float4* __restrict__ hp =
            h4 + (size_t)n * (KD / 4) + s * SLICE_F4 + tl;

        // 8 independent streaming (evict-first) loads in flight.
        float4 h[K];
        #pragma unroll
        for (int m = 0; m < K; m++) {
            h[m] = __ldcs(hp + m * (D / 4));
        }

        float4 acc = breg;
        #pragma unroll
        for (int m = 0; m < K; m++) {
            const float4 w =
                *reinterpret_cast<const float4*>(&wd[m][4 * tl]);  // LDS.128
            acc.x = fmaf(h[m].x, w.x, acc.x);
            acc.y = fmaf(h[m].y, w.y, acc.y);
            acc.z = fmaf(h[m].z, w.z, acc.z);
            acc.w = fmaf(h[m].w, w.w, acc.w);
        }

        // Write-back store: dirty lines park in L2, flush in bursts.
        o4[(size_t)n * (D / 4) + s * SLICE_F4 + tl] = acc;
    }
}

extern "C" void kernel_launch(void* const* d_in, const int* in_sizes, int n_in,
                              void* d_out, int out_size) {
    const float* h_r = (const float*)d_in[0];
    const float* W   = (const float*)d_in[1];
    const float* b   = (const float*)d_in[2];
    float* out       = (float*)d_out;

    const int n_rows = in_sizes[0] / KD;   // 8192

    imputation_kernel<<<GRID, THREADS>>>(h_r, W, b, out, n_rows);
}